// round 15
// baseline (speedup 1.0000x reference)
#include <cuda_runtime.h>
#include <cuda_fp16.h>
#include <stdint.h>

#define NPTS 131072
#define NM   34
#define NK   15
#define CIN  32
#define COUT 64
#define KT2  512                 // padded/permuted K dim (8 pairs * 64)
#define INV_SIGMA 25.0f          // 1 / 0.04
#define BN_EPS 1e-5f
#define NEG_SLOPE 0.2f

// ---- device scratch (no allocations allowed) ----
__device__ __align__(16) __half g_wf[(size_t)NPTS * KT2];       // 134 MB
__device__ __align__(16) __half g_wh_hi[KT2 * COUT];            // 64 KB (permuted)
__device__ __align__(16) __half g_wh_lo[KT2 * COUT];            // 64 KB (permuted)
__device__ __align__(16) float4 g_xyz4[NPTS];                   // 2 MB
__device__ float  g_raw[(size_t)NPTS * COUT];                   // 33.5 MB
__device__ float  g_accum[2 * COUT];

// ---- packed f32x2 helpers ----
__device__ __forceinline__ unsigned long long ffma2(unsigned long long a,
                                                    unsigned long long b,
                                                    unsigned long long c) {
    unsigned long long d;
    asm("fma.rn.f32x2 %0, %1, %2, %3;" : "=l"(d) : "l"(a), "l"(b), "l"(c));
    return d;
}
__device__ __forceinline__ unsigned long long pack2(float lo, float hi) {
    unsigned long long d;
    asm("mov.b64 %0, {%1, %2};" : "=l"(d) : "f"(lo), "f"(hi));
    return d;
}
__device__ __forceinline__ void unpack2(unsigned long long v, float& lo, float& hi) {
    asm("mov.b64 {%0, %1}, %2;" : "=f"(lo), "=f"(hi) : "l"(v));
}

// ---- tensor-core / async-copy helpers ----
__device__ __forceinline__ uint32_t smem_u32(const void* p) {
    return (uint32_t)__cvta_generic_to_shared(p);
}
__device__ __forceinline__ void cp16(uint32_t dst, const void* src) {
    asm volatile("cp.async.cg.shared.global [%0], [%1], 16;" :: "r"(dst), "l"(src));
}
#define CP_COMMIT() asm volatile("cp.async.commit_group;")
#define CP_WAIT(n)  asm volatile("cp.async.wait_group %0;" :: "n"(n))

__device__ __forceinline__ void ldm_x4(uint32_t& r0, uint32_t& r1,
                                       uint32_t& r2, uint32_t& r3, uint32_t addr) {
    asm volatile("ldmatrix.sync.aligned.m8n8.x4.shared.b16 {%0,%1,%2,%3}, [%4];"
                 : "=r"(r0), "=r"(r1), "=r"(r2), "=r"(r3) : "r"(addr));
}
__device__ __forceinline__ void ldm_x4_trans(uint32_t& r0, uint32_t& r1,
                                             uint32_t& r2, uint32_t& r3, uint32_t addr) {
    asm volatile("ldmatrix.sync.aligned.m8n8.x4.trans.shared.b16 {%0,%1,%2,%3}, [%4];"
                 : "=r"(r0), "=r"(r1), "=r"(r2), "=r"(r3) : "r"(addr));
}
__device__ __forceinline__ void mma16816(float& c0, float& c1, float& c2, float& c3,
                                         uint32_t a0, uint32_t a1, uint32_t a2, uint32_t a3,
                                         uint32_t b0, uint32_t b1) {
    asm volatile("mma.sync.aligned.m16n8k16.row.col.f32.f16.f16.f32 "
                 "{%0,%1,%2,%3}, {%4,%5,%6,%7}, {%8,%9}, {%0,%1,%2,%3};"
                 : "+f"(c0), "+f"(c1), "+f"(c2), "+f"(c3)
                 : "r"(a0), "r"(a1), "r"(a2), "r"(a3), "r"(b0), "r"(b1));
}

// ================= stage 0: repack xyz + permuted split W + zero accum =========
// W permutation: new row r' = (k>>1)*64 + c*2 + (k&1); rows with k==15 are zero.
__global__ __launch_bounds__(256)
void prep_kernel(const float* __restrict__ xyz,
                 const float* __restrict__ weight)
{
    const int b = blockIdx.x;
    if (b < NPTS / 256) {
        int n = b * 256 + threadIdx.x;
        g_xyz4[n] = make_float4(xyz[n * 3 + 0], xyz[n * 3 + 1], xyz[n * 3 + 2], 0.f);
    } else {
        int wb = b - NPTS / 256;                 // 0..7
        for (int j = 0; j < 16; j++) {
            int r  = wb * 4096 + j * 256 + threadIdx.x;   // 0..32767
            int rp = r >> 6;                               // permuted row 0..511
            int d  = r & 63;
            int jj  = rp >> 6;
            int rem = rp & 63;
            int c   = rem >> 1;
            int p   = rem & 1;
            int k   = 2 * jj + p;
            float w = (k < NK) ? weight[((k << 5) + c) * 64 + d] : 0.f;
            __half h = __float2half_rn(w);
            g_wh_hi[r] = h;
            g_wh_lo[r] = __float2half_rn(w - __half2float(h));
        }
        if (wb == 0 && threadIdx.x < 2 * COUT) g_accum[threadIdx.x] = 0.f;
    }
}

// ================= stage 1: wf (fp16, permuted pair layout) =================
// 128 threads, 4 warps, 2 points per warp, lane = input channel
__global__ __launch_bounds__(128)
void kpconv_wf(const float* __restrict__ feats,
               const int*   __restrict__ nbr,
               const float* __restrict__ kpts)
{
    __shared__ float4 sm_kp[16];                       // (-2k, |k|^2)
    __shared__ float4 sm_nb[4][2][NM];                 // nb xyz + |nb|^2
    __shared__ int    sm_idx[4][2][NM];
    __shared__ int    sm_act[4][NM];
    __shared__ int    sm_cm[4][36];
    __shared__ __align__(16) float sm_w[4][NM * 16];   // m-major, k stride 1

    const int tid  = threadIdx.x;
    const int lane = tid & 31;
    const int warp = tid >> 5;

    if (tid < 16) {
        float4 kp = make_float4(0.f, 0.f, 0.f, 0.f);
        if (tid < NK) {
            float kx = kpts[tid * 3 + 0];
            float ky = kpts[tid * 3 + 1];
            float kz = kpts[tid * 3 + 2];
            kp = make_float4(-2.f * kx, -2.f * ky, -2.f * kz,
                             fmaf(kx, kx, fmaf(ky, ky, kz * kz)));
        }
        sm_kp[tid] = kp;
    }
    __syncthreads();

    const int nbase = blockIdx.x * 8 + warp * 2;

    // ---- phase 0: gather BOTH points (latency overlaps later compute) ----
    #pragma unroll
    for (int i = 0; i < 2; i++) {
        const int n = nbase + i;
        const float4 c4 = g_xyz4[n];
        #pragma unroll
        for (int j = 0; j < 2; j++) {
            int m = j * 32 + lane;
            if (m < NM) {
                int idx = nbr[n * NM + m];
                int ci  = (idx < NPTS) ? idx : 0;          // shadow guard
                float4 p = __ldg(&g_xyz4[ci]);
                float vx = p.x - c4.x, vy = p.y - c4.y, vz = p.z - c4.z;
                if (idx >= NPTS) { vx = 1e6f; vy = 1e6f; vz = 1e6f; }
                float s = fmaf(vx, vx, fmaf(vy, vy, vz * vz));
                sm_nb[warp][i][m]  = make_float4(vx, vy, vz, s);
                sm_idx[warp][i][m] = ci;
            }
        }
    }
    __syncwarp();

    #pragma unroll
    for (int i = 0; i < 2; i++) {
        const int n = nbase + i;

        // influence weights w[m*16+k] + per-m activity mask
        #pragma unroll
        for (int it = 0; it < 17; it++) {
            int p = it * 32 + lane;                        // 0..543
            int m = p >> 4;
            int k = p & 15;
            float4 nb = sm_nb[warp][i][m];
            float4 kp = sm_kp[k];
            float d2 = fmaf(kp.x, nb.x,
                       fmaf(kp.y, nb.y,
                       fmaf(kp.z, nb.z, nb.w + kp.w)));
            d2 = fmaxf(d2, 0.f);                           // guard tiny negatives
            float w  = fmaf(sqrtf(d2), -INV_SIGMA, 1.f);
            bool on  = (w > 0.f) && (k < 15);
            unsigned bal = __ballot_sync(0xffffffffu, on);
            sm_w[warp][p] = on ? w : 0.f;
            if (lane == 0)  sm_act[warp][it * 2]     = (int)(bal & 0xffffu);
            if (lane == 16) sm_act[warp][it * 2 + 1] = (int)(bal >> 16);
        }
        __syncwarp();

        // compact the active-m list (warp-uniform count)
        int cnt = 0;
        #pragma unroll
        for (int j = 0; j < 2; j++) {
            int m = j * 32 + lane;
            bool on = (m < NM) && (sm_act[warp][m] != 0);
            unsigned bal = __ballot_sync(0xffffffffu, on);
            if (on) {
                int pos = cnt + __popc(bal & ((1u << lane) - 1u));
                sm_cm[warp][pos] = m;
            }
            cnt += __popc(bal);
        }
        __syncwarp();

        // accumulation over compacted list, 8-deep load batching
        unsigned long long wf2[8];
        #pragma unroll
        for (int j = 0; j < 8; j++) wf2[j] = 0ull;

        for (int j0 = 0; j0 < cnt; j0 += 8) {
            float f[8];
            int   mm[8];
            #pragma unroll
            for (int t = 0; t < 8; t++) {
                int jt = j0 + t;
                bool v = (jt < cnt);
                mm[t] = sm_cm[warp][v ? jt : j0];
                f[t]  = 0.f;
                if (v)
                    f[t] = __ldg(&feats[(size_t)sm_idx[warp][i][mm[t]] * CIN + lane]);
            }
            #pragma unroll
            for (int t = 0; t < 8; t++) {
                unsigned long long ff = pack2(f[t], f[t]);
                const ulonglong2* wp = (const ulonglong2*)&sm_w[warp][mm[t] * 16];
                #pragma unroll
                for (int q = 0; q < 4; q++) {
                    ulonglong2 wv = wp[q];                 // LDS.128 broadcast
                    wf2[2 * q]     = ffma2(ff, wv.x, wf2[2 * q]);
                    wf2[2 * q + 1] = ffma2(ff, wv.y, wf2[2 * q + 1]);
                }
            }
        }

        // store: pair-major permuted layout, col = j*64 + lane*2 + parity
        __half2* dst = (__half2*)&g_wf[(size_t)n * KT2 + lane * 2];
        #pragma unroll
        for (int j = 0; j < 8; j++) {
            float a, b;
            unpack2(wf2[j], a, b);                         // k=2j, k=2j+1
            dst[j * 32] = __floats2half2_rn(a, b);         // one STG.32
        }
        __syncwarp();
    }
}

// ================= stage 2: pipelined HMMA GEMM [N,512]x[512,64] =================
// 256 threads = 8 warps; warp w owns rows [16w,16w+16), all 64 cols.
__global__ __launch_bounds__(256)
void gemm_kernel()
{
    __shared__ __align__(16) __half As[2][128][40];
    __shared__ __align__(16) __half Bh[2][32][72];
    __shared__ __align__(16) __half Bl[2][32][72];
    __shared__ float sm_bn[2 * COUT];

    const int tid  = threadIdx.x;
    const int lane = tid & 31;
    const int warp = tid >> 5;
    const int row0 = blockIdx.x * 128;

    if (tid < 2 * COUT) sm_bn[tid] = 0.f;

    float acc[8][4];
    #pragma unroll
    for (int nt = 0; nt < 8; nt++)
        #pragma unroll
        for (int c = 0; c < 4; c++) acc[nt][c] = 0.f;

    // ldmatrix lane address bases (per buffer)
    const int arow = warp * 16 + (lane & 15);
    const int acol = (lane >> 4) * 8;
    const uint32_t aB0 = smem_u32(&As[0][arow][acol]);
    const uint32_t aB1 = smem_u32(&As[1][arow][acol]);
    const int brow = ((lane >> 3) & 1) * 8 + (lane & 7);
    const int bcol = (lane >> 4) * 8;
    const uint32_t bhB0 = smem_u32(&Bh[0][brow][bcol]);
    const uint32_t bhB1 = smem_u32(&Bh[1][brow][bcol]);
    const uint32_t blB0 = smem_u32(&Bl[0][brow][bcol]);
    const uint32_t blB1 = smem_u32(&Bl[1][brow][bcol]);

    const int br = tid >> 3, bq = tid & 7;

    #define LOAD_TILE(kc, buf)                                                  \
    do {                                                                        \
        _Pragma("unroll")                                                       \
        for (int j = 0; j < 2; j++) {                                           \
            int c = tid + j * 256;                                              \
            int r = c >> 2, q = c & 3;                                          \
            cp16(smem_u32(&As[buf][r][q * 8]),                                  \
                 &g_wf[(size_t)(row0 + r) * KT2 + (kc) * 32 + q * 8]);          \
        }                                                                       \
        cp16(smem_u32(&Bh[buf][br][bq * 8]),                                    \
             &g_wh_hi[((kc) * 32 + br) * COUT + bq * 8]);                       \
        cp16(smem_u32(&Bl[buf][br][bq * 8]),                                    \
             &g_wh_lo[((kc) * 32 + br) * COUT + bq * 8]);                       \
    } while (0)

    LOAD_TILE(0, 0);
    CP_COMMIT();

    for (int kc = 0; kc < KT2 / 32; kc++) {
        const int buf = kc & 1;
        if (kc < KT2 / 32 - 1) {
            LOAD_TILE(kc + 1, buf ^ 1);
            CP_COMMIT();
            CP_WAIT(1);
        } else {
            CP_WAIT(0);
        }
        __syncthreads();

        const uint32_t aBase  = buf ? aB1 : aB0;
        const uint32_t bhBase = buf ? bhB1 : bhB0;
        const uint32_t blBase = buf ? blB1 : blB0;

        #pragma unroll
        for (int ks = 0; ks < 2; ks++) {
            uint32_t ah[4];
            ldm_x4(ah[0], ah[1], ah[2], ah[3], aBase + ks * 32);   // +16 halves

            uint32_t bh[8][2], bl[8][2];
            #pragma unroll
            for (int np = 0; np < 4; np++) {
                uint32_t r0, r1, r2, r3;
                ldm_x4_trans(r0, r1, r2, r3, bhBase + ks * 16 * 144 + np * 32);
                bh[2 * np][0] = r0; bh[2 * np][1] = r1;
                bh[2 * np + 1][0] = r2; bh[2 * np + 1][1] = r3;
                ldm_x4_trans(r0, r1, r2, r3, blBase + ks * 16 * 144 + np * 32);
                bl[2 * np][0] = r0; bl[2 * np][1] = r1;
                bl[2 * np + 1][0] = r2; bl[2 * np + 1][1] = r3;
            }
            #pragma unroll
            for (int nt = 0; nt < 8; nt++) {
                mma16816(acc[nt][0], acc[nt][1], acc[nt][2], acc[nt][3],
                         ah[0], ah[1], ah[2], ah[3], bh[nt][0], bh[nt][1]);
                mma16816(acc[nt][0], acc[nt][1], acc[nt][2], acc[nt][3],
                         ah[0], ah[1], ah[2], ah[3], bl[nt][0], bl[nt][1]);
            }
        }
        __syncthreads();
    }

    // epilogue: write raw out + BN partial sums
    const int g8 = lane >> 2, t4 = lane & 3;
    const int rA = row0 + warp * 16 + g8;
    const int rB = rA + 8;
    float lsum[16], lsq[16];
    #pragma unroll
    for (int nt = 0; nt < 8; nt++) {
        int col = nt * 8 + 2 * t4;
        *(float2*)&g_raw[(size_t)rA * COUT + col] = make_float2(acc[nt][0], acc[nt][1]);
        *(float2*)&g_raw[(size_t)rB * COUT + col] = make_float2(acc[nt][2], acc[nt][3]);
        lsum[2 * nt]     = acc[nt][0] + acc[nt][2];
        lsum[2 * nt + 1] = acc[nt][1] + acc[nt][3];
        lsq[2 * nt]      = fmaf(acc[nt][0], acc[nt][0], acc[nt][2] * acc[nt][2]);
        lsq[2 * nt + 1]  = fmaf(acc[nt][1], acc[nt][1], acc[nt][3] * acc[nt][3]);
    }
    #pragma unroll
    for (int mask = 4; mask <= 16; mask <<= 1) {
        #pragma unroll
        for (int v = 0; v < 16; v++) {
            lsum[v] += __shfl_xor_sync(0xffffffffu, lsum[v], mask);
            lsq[v]  += __shfl_xor_sync(0xffffffffu, lsq[v],  mask);
        }
    }
    if (g8 == 0) {
        #pragma unroll
        for (int nt = 0; nt < 8; nt++) {
            int col = nt * 8 + 2 * t4;
            atomicAdd(&sm_bn[col],            lsum[2 * nt]);
            atomicAdd(&sm_bn[col + 1],        lsum[2 * nt + 1]);
            atomicAdd(&sm_bn[COUT + col],     lsq[2 * nt]);
            atomicAdd(&sm_bn[COUT + col + 1], lsq[2 * nt + 1]);
        }
    }
    __syncthreads();
    if (tid < 2 * COUT) atomicAdd(&g_accum[tid], sm_bn[tid]);
}

// ================= finalize (computes BN params per-block) =================
__global__ __launch_bounds__(256)
void finalize_kernel(float* __restrict__ out,
                     const float* __restrict__ gamma,
                     const float* __restrict__ beta)
{
    __shared__ float sp[2 * COUT];
    const int t = threadIdx.x;
    if (t < COUT) {
        const float invN = 1.0f / (float)NPTS;
        float mean = g_accum[t] * invN;
        float var  = g_accum[COUT + t] * invN - mean * mean;
        float inv  = rsqrtf(var + BN_EPS);
        float sc   = gamma[t] * inv;
        sp[t]        = sc;
        sp[COUT + t] = fmaf(-mean, sc, beta[t]);
    }
    __syncthreads();

    int i = blockIdx.x * blockDim.x + t;             // over N*64/4 float4s
    float4 v = *(const float4*)&g_raw[(size_t)i * 4];
    int d4 = (i & 15) * 4;
    float x0 = fmaf(v.x, sp[d4 + 0], sp[COUT + d4 + 0]);
    float x1 = fmaf(v.y, sp[d4 + 1], sp[COUT + d4 + 1]);
    float x2 = fmaf(v.z, sp[d4 + 2], sp[COUT + d4 + 2]);
    float x3 = fmaf(v.w, sp[d4 + 3], sp[COUT + d4 + 3]);
    x0 = (x0 >= 0.f) ? x0 : NEG_SLOPE * x0;
    x1 = (x1 >= 0.f) ? x1 : NEG_SLOPE * x1;
    x2 = (x2 >= 0.f) ? x2 : NEG_SLOPE * x2;
    x3 = (x3 >= 0.f) ? x3 : NEG_SLOPE * x3;
    ((float4*)out)[i] = make_float4(x0, x1, x2, x3);
}

extern "C" void kernel_launch(void* const* d_in, const int* in_sizes, int n_in,
                              void* d_out, int out_size)
{
    const float* xyz    = (const float*)d_in[0];
    const float* feats  = (const float*)d_in[1];
    const int*   nbr    = (const int*)d_in[2];
    const float* weight = (const float*)d_in[3];
    const float* kpts   = (const float*)d_in[4];
    const float* gamma  = (const float*)d_in[5];
    const float* beta   = (const float*)d_in[6];
    float* out = (float*)d_out;

    prep_kernel<<<NPTS / 256 + 8, 256>>>(xyz, weight);
    kpconv_wf<<<NPTS / 8, 128>>>(feats, nbr, kpts);
    gemm_kernel<<<NPTS / 128, 256>>>();
    finalize_kernel<<<(NPTS * COUT / 4) / 256, 256>>>(out, gamma, beta);
}